// round 3
// baseline (speedup 1.0000x reference)
#include <cuda_runtime.h>

// Problem constants (fixed by the reference).
#define NN 100000
#define DD 64
#define NE 1600000
#define NROW4 16            // float4s per 64-float row

// Chebyshev coefficients for lambda_max = 2.0 (kept general; constant-fold to
// c1a=-1, c1b=0, c2a=-2, c2b=0).
#define C1A (-2.0f / 2.0f)
#define C1B (2.0f / 2.0f - 1.0f)
#define C2A (-4.0f / 2.0f)
#define C2B (4.0f / 2.0f - 2.0f)

// Scratch (device globals: no allocation allowed in kernel_launch).
__device__ float  g_deg [NN];
__device__ float  g_norm[NN];
__device__ float4 g_xs  [NN * NROW4];   // scaled features (reused between passes)
__device__ float4 g_h0  [NN * NROW4];   // scatter result pass 1
__device__ float4 g_h1  [NN * NROW4];   // scatter result pass 2

typedef unsigned long long ull;

// ---------------------------------------------------------------------------
// f32x2 packed-FMA helpers (Blackwell)
// ---------------------------------------------------------------------------
__device__ __forceinline__ ull pack2(float v) {
    ull r;
    asm("mov.b64 %0, {%1, %1};" : "=l"(r) : "f"(v));
    return r;
}
__device__ __forceinline__ void fma2(ull& d, ull a, ull b) {
    asm("fma.rn.f32x2 %0, %1, %2, %0;" : "+l"(d) : "l"(a), "l"(b));
}
__device__ __forceinline__ float2 unpack2(ull v) {
    float2 r;
    asm("mov.b64 {%0, %1}, %2;" : "=f"(r.x), "=f"(r.y) : "l"(v));
    return r;
}

// ---------------------------------------------------------------------------
// 1) degree histogram: deg[dst] += 1
// ---------------------------------------------------------------------------
__global__ void deg_kernel(const int4* __restrict__ dst4) {
    int t = blockIdx.x * blockDim.x + threadIdx.x;
    if (t < NE / 4) {
        int4 d = __ldg(dst4 + t);
        atomicAdd(&g_deg[d.x], 1.0f);
        atomicAdd(&g_deg[d.y], 1.0f);
        atomicAdd(&g_deg[d.z], 1.0f);
        atomicAdd(&g_deg[d.w], 1.0f);
    }
}

// ---------------------------------------------------------------------------
// 2) norm = rsqrt(max(deg,1));  xs = feat * norm   (row-scaled features)
// ---------------------------------------------------------------------------
__global__ void scale_kernel(const float4* __restrict__ feat4) {
    int t = blockIdx.x * blockDim.x + threadIdx.x;
    if (t < NN * NROW4) {
        int i = t >> 4;
        float nv = rsqrtf(fmaxf(g_deg[i], 1.0f));
        float4 f = __ldg(feat4 + t);
        f.x *= nv; f.y *= nv; f.z *= nv; f.w *= nv;
        g_xs[t] = f;
        if ((t & 15) == 0) g_norm[i] = nv;
    }
}

// ---------------------------------------------------------------------------
// 3) scatter: h[dst] += g_xs[src]  (16B vector reductions; one thread per
//    (edge, float4-chunk); 16 consecutive threads share one edge).
//    PASS selects destination buffer so no scratch pointers cross the ABI.
// ---------------------------------------------------------------------------
template <int PASS>
__global__ void scatter_kernel(const int* __restrict__ src,
                               const int* __restrict__ dst) {
    int t = blockIdx.x * blockDim.x + threadIdx.x;
    if (t < NE * NROW4) {
        int e = t >> 4;
        int c = t & 15;
        int s = __ldg(src + e);
        int d = __ldg(dst + e);
        float4 v = g_xs[(s << 4) + c];
        float4* hp = (PASS == 0 ? g_h0 : g_h1) + (d << 4) + c;
        float* p = reinterpret_cast<float*>(hp);
        asm volatile("red.global.add.v4.f32 [%0], {%1, %2, %3, %4};"
                     :: "l"(p), "f"(v.x), "f"(v.y), "f"(v.z), "f"(v.w)
                     : "memory");
    }
}

// ---------------------------------------------------------------------------
// 4) xs <- Tx1 * norm, where Tx1 = c1a*norm*h0 + c1b*feat
// ---------------------------------------------------------------------------
__global__ void rescale_kernel(const float4* __restrict__ feat4) {
    int t = blockIdx.x * blockDim.x + threadIdx.x;
    if (t < NN * NROW4) {
        int i = t >> 4;
        float nv = g_norm[i];
        float a = C1A * nv;
        float4 h = g_h0[t];
        float4 f = __ldg(feat4 + t);
        float4 r;
        r.x = (a * h.x + C1B * f.x) * nv;
        r.y = (a * h.y + C1B * f.y) * nv;
        r.z = (a * h.z + C1B * f.z) * nv;
        r.w = (a * h.w + C1B * f.w) * nv;
        g_xs[t] = r;
    }
}

// ---------------------------------------------------------------------------
// 5) fused epilogue GEMM:
//    t0 = feat;  t1 = c1a*n*h0 + c1b*t0;  t2 = c2a*n*h1 + c2b*t1 - t0
//    out = t0@W0 + t1@W1 + t2@W2 + bias
//    Block: 256 threads = 4 col-groups (16 cols, warp-uniform) x 64 row-groups
//    (4 rows each). W (48KB) in shared; packed f32x2 accumulators.
// ---------------------------------------------------------------------------
__global__ __launch_bounds__(256) void final_kernel(
    const float4* __restrict__ feat4,
    const float4* __restrict__ W4,
    const float4* __restrict__ bias4,
    float4* __restrict__ out4) {
    __shared__ __align__(16) float Ws[3 * 64 * 64];   // 49152 B
    {
        float4* Ws4 = reinterpret_cast<float4*>(Ws);
        for (int i = threadIdx.x; i < 3 * 64 * 16; i += 256)
            Ws4[i] = __ldg(W4 + i);
    }
    __syncthreads();

    const int cg   = threadIdx.x >> 6;   // col group: cols [16*cg, 16*cg+16)
    const int rg   = threadIdx.x & 63;
    const int base = blockIdx.x * 256;

    int   rows[4];
    bool  valid[4];
    float n[4];
#pragma unroll
    for (int r = 0; r < 4; r++) {
        int row  = base + rg + 64 * r;
        valid[r] = row < NN;
        rows[r]  = valid[r] ? row : 0;
        n[r]     = g_norm[rows[r]];
    }

    ull acc[4][8];
#pragma unroll
    for (int r = 0; r < 4; r++)
#pragma unroll
        for (int cp = 0; cp < 8; cp++) acc[r][cp] = 0ULL;

    const ulonglong2* Wp = reinterpret_cast<const ulonglong2*>(Ws);
    // ulonglong2 index: float index / 4 = k*1024 + d*16 + cg*4 + j

    for (int dc = 0; dc < 16; dc++) {          // d in chunks of 4
        float4 a0[4], a1[4], a2[4];
#pragma unroll
        for (int r = 0; r < 4; r++) {
            int b = (rows[r] << 4) + dc;
            a0[r] = __ldg(feat4 + b);
            a1[r] = g_h0[b];
            a2[r] = g_h1[b];
        }
#pragma unroll
        for (int s = 0; s < 4; s++) {
            const int d = dc * 4 + s;
            ull tt[3][4];
#pragma unroll
            for (int r = 0; r < 4; r++) {
                float t0  = reinterpret_cast<const float*>(&a0[r])[s];
                float h0v = reinterpret_cast<const float*>(&a1[r])[s];
                float h1v = reinterpret_cast<const float*>(&a2[r])[s];
                float t1 = fmaf(C1A * n[r], h0v, C1B * t0);
                float t2 = fmaf(C2A * n[r], h1v, fmaf(C2B, t1, -t0));
                tt[0][r] = pack2(t0);
                tt[1][r] = pack2(t1);
                tt[2][r] = pack2(t2);
            }
#pragma unroll
            for (int k = 0; k < 3; k++) {
                const ulonglong2* p = Wp + (k * 1024 + d * 16 + cg * 4);
                ull w[8];
#pragma unroll
                for (int j = 0; j < 4; j++) {
                    ulonglong2 v = p[j];       // LDS.128, warp-uniform broadcast
                    w[2 * j]     = v.x;
                    w[2 * j + 1] = v.y;
                }
#pragma unroll
                for (int r = 0; r < 4; r++)
#pragma unroll
                    for (int cp = 0; cp < 8; cp++)
                        fma2(acc[r][cp], tt[k][r], w[cp]);
            }
        }
    }

    float4 b4[4];
#pragma unroll
    for (int j = 0; j < 4; j++) b4[j] = __ldg(bias4 + cg * 4 + j);
#pragma unroll
    for (int r = 0; r < 4; r++) {
        if (!valid[r]) continue;
#pragma unroll
        for (int j = 0; j < 4; j++) {
            float2 lo = unpack2(acc[r][2 * j]);
            float2 hi = unpack2(acc[r][2 * j + 1]);
            float4 o;
            o.x = lo.x + b4[j].x;
            o.y = lo.y + b4[j].y;
            o.z = hi.x + b4[j].z;
            o.w = hi.y + b4[j].w;
            out4[(rows[r] << 4) + cg * 4 + j] = o;
        }
    }
}

// ---------------------------------------------------------------------------
// launch (graph-capturable: only async memsets + kernel launches)
// ---------------------------------------------------------------------------
extern "C" void kernel_launch(void* const* d_in, const int* in_sizes, int n_in,
                              void* d_out, int out_size) {
    const float* feat = (const float*)d_in[0];
    const float* W    = (const float*)d_in[1];
    const float* bias = (const float*)d_in[2];
    const int*   esrc = (const int*)d_in[3];
    const int*   edst = (const int*)d_in[4];
    float*       out  = (float*)d_out;

    void *p_deg = nullptr, *p_h0 = nullptr, *p_h1 = nullptr;
    cudaGetSymbolAddress(&p_deg, g_deg);
    cudaGetSymbolAddress(&p_h0,  g_h0);
    cudaGetSymbolAddress(&p_h1,  g_h1);
    cudaMemsetAsync(p_deg, 0, NN * sizeof(float));
    cudaMemsetAsync(p_h0,  0, NN * DD * sizeof(float));
    cudaMemsetAsync(p_h1,  0, NN * DD * sizeof(float));

    const int T = 256;

    deg_kernel<<<(NE / 4 + T - 1) / T, T>>>((const int4*)edst);
    scale_kernel<<<(NN * NROW4 + T - 1) / T, T>>>((const float4*)feat);
    scatter_kernel<0><<<(NE * NROW4 + T - 1) / T, T>>>(esrc, edst);
    rescale_kernel<<<(NN * NROW4 + T - 1) / T, T>>>((const float4*)feat);
    scatter_kernel<1><<<(NE * NROW4 + T - 1) / T, T>>>(esrc, edst);
    final_kernel<<<(NN + 255) / 256, 256>>>((const float4*)feat,
                                            (const float4*)W,
                                            (const float4*)bias,
                                            (float4*)out);
}